// round 3
// baseline (speedup 1.0000x reference)
#include <cuda_runtime.h>
#include <cuda_bf16.h>
#include <cstdint>

// RBFN: out[n] = b + sum_c W_c * exp(-sigma_c^2 * max(||x_n||^2 + ||c_c||^2 - 2 x_n.c_c, 0))
// N=131072, D=64, C=512.
// Build targets plain sm_103 (no 'a' feature) -> tcgen05 unavailable.
// Use baseline PTX tensor ISA: ldmatrix + mma.sync.m16n8k16 bf16/f32.
//
// Layout: 148 persistent CTAs x 256 threads. Per tile: 128 rows x 512 cols.
// Warp w owns columns [w*64, w*64+64) with B fragments register-resident
// for the entire kernel. Per-column constants (k1, kk, W) also in registers.

#define NROWS   131072
#define DDIM    64
#define CDIM    512
#define M_TILE  128
#define NTILES  (NROWS / M_TILE)   // 1024
#define GRID    148
#define NTHREADS 256

#define ROW_BYTES 128   // 64 bf16 per row

// dynamic smem layout (base 1024-aligned => swizzle valid)
#define SMEM_B     0                        // 512 * 128B = 65536
#define SMEM_A     (SMEM_B + 65536)         // 128 * 128B = 16384
#define SMEM_KK    (SMEM_A + 16384)         // float2[512] = 4096
#define SMEM_WS    (SMEM_KK + 4096)         // float[512]  = 2048
#define SMEM_X2    (SMEM_WS + 2048)         // float[128]  = 512
#define SMEM_PART  (SMEM_X2 + 512)          // float[8*128] = 4096
#define SMEM_TOTAL (SMEM_PART + 4096 + 128)

static __device__ __forceinline__ uint32_t smem_u32(const void* p) {
    uint32_t a;
    asm("{ .reg .u64 t; cvta.to.shared.u64 t, %1; cvt.u32.u64 %0, t; }" : "=r"(a) : "l"(p));
    return a;
}
static __device__ __forceinline__ uint32_t swz(uint32_t off) {
    return off ^ ((off >> 3) & 0x70);
}
static __device__ __forceinline__ uint32_t pack2(float a, float b) {
    __nv_bfloat162 h = __floats2bfloat162_rn(a, b);
    return *reinterpret_cast<uint32_t*>(&h);
}
static __device__ __forceinline__ float ex2f(float e) {
    float r; asm("ex2.approx.ftz.f32 %0, %1;" : "=f"(r) : "f"(e)); return r;
}
static __device__ __forceinline__ uint32_t lds32(uint32_t addr) {
    uint32_t v; asm volatile("ld.shared.b32 %0, [%1];" : "=r"(v) : "r"(addr)); return v;
}

#define STS128(addr, v) \
    asm volatile("st.shared.v4.b32 [%0], {%1,%2,%3,%4};" :: "r"(addr), "r"((v).x), "r"((v).y), "r"((v).z), "r"((v).w) : "memory")

#define LDMATRIX_X4(r0, r1, r2, r3, addr) \
    asm volatile("ldmatrix.sync.aligned.m8n8.x4.shared.b16 {%0,%1,%2,%3}, [%4];" \
        : "=r"(r0), "=r"(r1), "=r"(r2), "=r"(r3) : "r"(addr))

#define MMA16816(c0, c1, c2, c3, a0, a1, a2, a3, b0, b1) \
    asm volatile("mma.sync.aligned.m16n8k16.row.col.f32.bf16.bf16.f32 " \
        "{%0,%1,%2,%3}, {%4,%5,%6,%7}, {%8,%9}, {%0,%1,%2,%3};" \
        : "+f"(c0), "+f"(c1), "+f"(c2), "+f"(c3) \
        : "r"(a0), "r"(a1), "r"(a2), "r"(a3), "r"(b0), "r"(b1))

__global__ void __launch_bounds__(NTHREADS, 1)
rbfn_kernel(const float* __restrict__ x,
            const float* __restrict__ centres,
            const float* __restrict__ sigmas,
            const float* __restrict__ W,
            const float* __restrict__ bptr,
            float* __restrict__ out)
{
    extern __shared__ char smem[];
    const uint32_t sbase = smem_u32(smem);
    const int tid = threadIdx.x;
    const int wid = tid >> 5;
    const int lid = tid & 31;

    const float LOG2E = 1.4426950408889634f;
    float2* kk12 = reinterpret_cast<float2*>(smem + SMEM_KK);
    float*  wcs  = reinterpret_cast<float*>(smem + SMEM_WS);
    float*  x2s  = reinterpret_cast<float*>(smem + SMEM_X2);
    float*  part = reinterpret_cast<float*>(smem + SMEM_PART);

    // ---- one-time: centres -> bf16 SW128 smem, per-centre constants ----
    for (int c = tid; c < CDIM; c += NTHREADS) {
        const float4* cr = reinterpret_cast<const float4*>(centres + c * DDIM);
        float c2 = 0.f;
#pragma unroll
        for (int j = 0; j < 8; j++) {
            float4 v0 = cr[2 * j];
            float4 v1 = cr[2 * j + 1];
            c2 += v0.x * v0.x + v0.y * v0.y + v0.z * v0.z + v0.w * v0.w
                + v1.x * v1.x + v1.y * v1.y + v1.z * v1.z + v1.w * v1.w;
            uint4 pk;
            pk.x = pack2(v0.x, v0.y); pk.y = pack2(v0.z, v0.w);
            pk.z = pack2(v1.x, v1.y); pk.w = pack2(v1.z, v1.w);
            STS128(sbase + SMEM_B + swz((uint32_t)(c * ROW_BYTES + j * 16)), pk);
        }
        float s = sigmas[c];
        float s2 = s * s;
        kk12[c] = make_float2(2.f * s2 * LOG2E, -s2 * c2 * LOG2E);
        wcs[c] = W[c];
    }
    __syncthreads();

    // ---- one-time: B fragments -> registers (warp owns cols wid*64..+63) ----
    // b frag n8k16: lane holds (k=(l&3)*2, n=l>>2) pairs; b1 at k+8.
    uint32_t breg[8][4][2];
#pragma unroll
    for (int nf = 0; nf < 8; nf++) {
#pragma unroll
        for (int k = 0; k < 4; k++) {
            int c = wid * 64 + nf * 8 + (lid >> 2);
            uint32_t byte0 = (uint32_t)(c * ROW_BYTES) + (uint32_t)((k * 16 + (lid & 3) * 2) * 2);
            breg[nf][k][0] = lds32(sbase + SMEM_B + swz(byte0));
            breg[nf][k][1] = lds32(sbase + SMEM_B + swz(byte0 + 16));
        }
    }

    // ---- one-time: per-lane column constants -> registers ----
    // lane's columns: wid*64 + nf*8 + (lid&3)*2 + j, j in {0,1}
    float k1v[8][2], kkv[8][2], wv[8][2];
#pragma unroll
    for (int nf = 0; nf < 8; nf++) {
#pragma unroll
        for (int j = 0; j < 2; j++) {
            int c = wid * 64 + nf * 8 + (lid & 3) * 2 + j;
            float2 kv = kk12[c];
            k1v[nf][j] = kv.x;
            kkv[nf][j] = kv.y;
            wv[nf][j]  = wcs[c];
        }
    }
    const float bval = *bptr;

    for (int tile = blockIdx.x; tile < NTILES; tile += GRID) {
        const int row0 = tile * M_TILE;

        __syncthreads();   // prev tile's smem reads done

        // ---- load x tile: bf16 SW128 A + ||x||^2 ----
        if (tid < M_TILE) {
            const float4* xr = reinterpret_cast<const float4*>(x + (size_t)(row0 + tid) * DDIM);
            float x2 = 0.f;
#pragma unroll
            for (int j = 0; j < 8; j++) {
                float4 v0 = xr[2 * j];
                float4 v1 = xr[2 * j + 1];
                x2 += v0.x * v0.x + v0.y * v0.y + v0.z * v0.z + v0.w * v0.w
                    + v1.x * v1.x + v1.y * v1.y + v1.z * v1.z + v1.w * v1.w;
                uint4 pk;
                pk.x = pack2(v0.x, v0.y); pk.y = pack2(v0.z, v0.w);
                pk.z = pack2(v1.x, v1.y); pk.w = pack2(v1.z, v1.w);
                STS128(sbase + SMEM_A + swz((uint32_t)(tid * ROW_BYTES + j * 16)), pk);
            }
            x2s[tid] = x2;
        }
        __syncthreads();

        // ---- 8 m-fragments of 16 rows each; all warps cover all rows ----
#pragma unroll 1
        for (int mf = 0; mf < 8; mf++) {
            // A fragments via ldmatrix.x4 (rows mf*16..+15, 4 k-steps of 16)
            uint32_t a[4][4];
            const uint32_t arow = (uint32_t)(mf * 16 + (lid & 15));
#pragma unroll
            for (int k = 0; k < 4; k++) {
                uint32_t kbyte = (uint32_t)(k * 32 + ((lid >> 4) * 16));
                uint32_t addr = sbase + SMEM_A + swz(arow * ROW_BYTES + kbyte);
                LDMATRIX_X4(a[k][0], a[k][1], a[k][2], a[k][3], addr);
            }

            float acc[8][4];
#pragma unroll
            for (int nf = 0; nf < 8; nf++) {
                acc[nf][0] = 0.f; acc[nf][1] = 0.f; acc[nf][2] = 0.f; acc[nf][3] = 0.f;
#pragma unroll
                for (int k = 0; k < 4; k++) {
                    MMA16816(acc[nf][0], acc[nf][1], acc[nf][2], acc[nf][3],
                             a[k][0], a[k][1], a[k][2], a[k][3],
                             breg[nf][k][0], breg[nf][k][1]);
                }
            }

            // ---- fused epilogue ----
            const int r0 = mf * 16 + (lid >> 2);
            const int r1 = r0 + 8;
            const float hx20 = 0.5f * x2s[r0];
            const float hx21 = 0.5f * x2s[r1];
            float acc0 = 0.f, acc1 = 0.f;
#pragma unroll
            for (int nf = 0; nf < 8; nf++) {
#pragma unroll
                for (int j = 0; j < 2; j++) {
                    float e0 = fmaf(k1v[nf][j], acc[nf][j] - hx20, kkv[nf][j]);
                    if (e0 > -126.f)
                        acc0 = fmaf(ex2f(fminf(e0, 0.f)), wv[nf][j], acc0);
                    float e1 = fmaf(k1v[nf][j], acc[nf][2 + j] - hx21, kkv[nf][j]);
                    if (e1 > -126.f)
                        acc1 = fmaf(ex2f(fminf(e1, 0.f)), wv[nf][j], acc1);
                }
            }
            // reduce over the 4 lanes sharing a row (lane&3 group)
            acc0 += __shfl_xor_sync(0xffffffffu, acc0, 1);
            acc0 += __shfl_xor_sync(0xffffffffu, acc0, 2);
            acc1 += __shfl_xor_sync(0xffffffffu, acc1, 1);
            acc1 += __shfl_xor_sync(0xffffffffu, acc1, 2);
            if ((lid & 3) == 0) {
                part[wid * M_TILE + r0] = acc0;
                part[wid * M_TILE + r1] = acc1;
            }
        }

        __syncthreads();

        if (tid < M_TILE) {
            float s = bval;
#pragma unroll
            for (int w = 0; w < 8; w++) s += part[w * M_TILE + tid];
            out[row0 + tid] = s;
        }
    }
}

extern "C" void kernel_launch(void* const* d_in, const int* in_sizes, int n_in,
                              void* d_out, int out_size) {
    const float* x       = (const float*)d_in[0];
    const float* centres = (const float*)d_in[1];
    const float* sigmas  = (const float*)d_in[2];
    const float* W       = (const float*)d_in[3];
    const float* b       = (const float*)d_in[4];
    float* out = (float*)d_out;

    cudaFuncSetAttribute(rbfn_kernel, cudaFuncAttributeMaxDynamicSharedMemorySize, SMEM_TOTAL);
    rbfn_kernel<<<GRID, NTHREADS, SMEM_TOTAL>>>(x, centres, sigmas, W, b, out);
}

// round 4
// speedup vs baseline: 1.0428x; 1.0428x over previous
#include <cuda_runtime.h>
#include <cuda_bf16.h>
#include <cstdint>

// RBFN: out[n] = b + sum_c W_c * exp(-sigma_c^2 * max(||x_n||^2 + ||c_c||^2 - 2 x_n.c_c, 0))
// N=131072, D=64, C=512.  ldmatrix + mma.sync.m16n8k16 bf16/f32 (plain sm_103 ISA).
//
// R3 -> R4: 512 threads (16 warps, 4/SMSP) each owning 32 columns; double-buffered
// A tile with software-pipelined x prefetch (LDG+pack in regs overlaps MMA).

#define NROWS   131072
#define DDIM    64
#define CDIM    512
#define M_TILE  128
#define NTILES  (NROWS / M_TILE)   // 1024
#define GRID    148
#define NTHREADS 512
#define NWARPS  16

#define ROW_BYTES 128   // 64 bf16 per row

// smem layout (dynamic base is 1024-aligned)
#define SMEM_B     0                        // 512 * 128B = 65536
#define SMEM_A     (SMEM_B + 65536)         // 2 buffers * 16384
#define SMEM_KK    (SMEM_A + 2*16384)       // float2[512] = 4096
#define SMEM_WS    (SMEM_KK + 4096)         // float[512]  = 2048
#define SMEM_X2    (SMEM_WS + 2048)         // 2 * float[128] = 1024
#define SMEM_PART  (SMEM_X2 + 1024)         // float[16*128] = 8192
#define SMEM_TOTAL (SMEM_PART + 8192 + 128)

static __device__ __forceinline__ uint32_t smem_u32(const void* p) {
    uint32_t a;
    asm("{ .reg .u64 t; cvta.to.shared.u64 t, %1; cvt.u32.u64 %0, t; }" : "=r"(a) : "l"(p));
    return a;
}
static __device__ __forceinline__ uint32_t swz(uint32_t off) {
    return off ^ ((off >> 3) & 0x70);
}
static __device__ __forceinline__ uint32_t pack2(float a, float b) {
    __nv_bfloat162 h = __floats2bfloat162_rn(a, b);
    return *reinterpret_cast<uint32_t*>(&h);
}
static __device__ __forceinline__ float ex2f(float e) {
    float r; asm("ex2.approx.ftz.f32 %0, %1;" : "=f"(r) : "f"(e)); return r;
}
static __device__ __forceinline__ uint32_t lds32(uint32_t addr) {
    uint32_t v; asm volatile("ld.shared.b32 %0, [%1];" : "=r"(v) : "r"(addr)); return v;
}

#define STS128(addr, v) \
    asm volatile("st.shared.v4.b32 [%0], {%1,%2,%3,%4};" :: "r"(addr), "r"((v).x), "r"((v).y), "r"((v).z), "r"((v).w) : "memory")

#define LDMATRIX_X4(r0, r1, r2, r3, addr) \
    asm volatile("ldmatrix.sync.aligned.m8n8.x4.shared.b16 {%0,%1,%2,%3}, [%4];" \
        : "=r"(r0), "=r"(r1), "=r"(r2), "=r"(r3) : "r"(addr))

#define MMA16816(c0, c1, c2, c3, a0, a1, a2, a3, b0, b1) \
    asm volatile("mma.sync.aligned.m16n8k16.row.col.f32.bf16.bf16.f32 " \
        "{%0,%1,%2,%3}, {%4,%5,%6,%7}, {%8,%9}, {%0,%1,%2,%3};" \
        : "+f"(c0), "+f"(c1), "+f"(c2), "+f"(c3) \
        : "r"(a0), "r"(a1), "r"(a2), "r"(a3), "r"(b0), "r"(b1))

__global__ void __launch_bounds__(NTHREADS, 1)
rbfn_kernel(const float* __restrict__ x,
            const float* __restrict__ centres,
            const float* __restrict__ sigmas,
            const float* __restrict__ W,
            const float* __restrict__ bptr,
            float* __restrict__ out)
{
    extern __shared__ char smem[];
    const uint32_t sbase = smem_u32(smem);
    const int tid = threadIdx.x;
    const int wid = tid >> 5;
    const int lid = tid & 31;

    const float LOG2E = 1.4426950408889634f;
    float2* kk12 = reinterpret_cast<float2*>(smem + SMEM_KK);
    float*  wcs  = reinterpret_cast<float*>(smem + SMEM_WS);
    float*  x2s  = reinterpret_cast<float*>(smem + SMEM_X2);   // [2][128]
    float*  part = reinterpret_cast<float*>(smem + SMEM_PART); // [16][128]

    // ---- one-time: centres -> bf16 SW128 smem, per-centre constants ----
    for (int c = tid; c < CDIM; c += NTHREADS) {
        const float4* cr = reinterpret_cast<const float4*>(centres + c * DDIM);
        float c2 = 0.f;
#pragma unroll
        for (int j = 0; j < 8; j++) {
            float4 v0 = cr[2 * j];
            float4 v1 = cr[2 * j + 1];
            c2 += v0.x * v0.x + v0.y * v0.y + v0.z * v0.z + v0.w * v0.w
                + v1.x * v1.x + v1.y * v1.y + v1.z * v1.z + v1.w * v1.w;
            uint4 pk;
            pk.x = pack2(v0.x, v0.y); pk.y = pack2(v0.z, v0.w);
            pk.z = pack2(v1.x, v1.y); pk.w = pack2(v1.z, v1.w);
            STS128(sbase + SMEM_B + swz((uint32_t)(c * ROW_BYTES + j * 16)), pk);
        }
        float s = sigmas[c];
        float s2 = s * s;
        kk12[c] = make_float2(2.f * s2 * LOG2E, -s2 * c2 * LOG2E);
        wcs[c] = W[c];
    }
    __syncthreads();

    // ---- one-time: B fragments -> registers (warp owns cols wid*32..+31) ----
    uint32_t breg[4][4][2];
#pragma unroll
    for (int nf = 0; nf < 4; nf++) {
#pragma unroll
        for (int k = 0; k < 4; k++) {
            int c = wid * 32 + nf * 8 + (lid >> 2);
            uint32_t byte0 = (uint32_t)(c * ROW_BYTES) + (uint32_t)((k * 16 + (lid & 3) * 2) * 2);
            breg[nf][k][0] = lds32(sbase + SMEM_B + swz(byte0));
            breg[nf][k][1] = lds32(sbase + SMEM_B + swz(byte0 + 16));
        }
    }

    // ---- one-time: per-lane column constants -> registers ----
    float k1v[4][2], kkv[4][2], wv[4][2];
#pragma unroll
    for (int nf = 0; nf < 4; nf++) {
#pragma unroll
        for (int j = 0; j < 2; j++) {
            int c = wid * 32 + nf * 8 + (lid & 3) * 2 + j;
            float2 kv = kk12[c];
            k1v[nf][j] = kv.x;
            kkv[nf][j] = kv.y;
            wv[nf][j]  = wcs[c];
        }
    }
    const float bval = *bptr;

    // ---- prologue: load first tile into buffer 0 ----
    int tile = blockIdx.x;
    if (tid < M_TILE && tile < NTILES) {
        const float4* xr = reinterpret_cast<const float4*>(x + (size_t)(tile * M_TILE + tid) * DDIM);
        float x2 = 0.f;
#pragma unroll
        for (int j = 0; j < 8; j++) {
            float4 v0 = xr[2 * j];
            float4 v1 = xr[2 * j + 1];
            x2 += v0.x * v0.x + v0.y * v0.y + v0.z * v0.z + v0.w * v0.w
                + v1.x * v1.x + v1.y * v1.y + v1.z * v1.z + v1.w * v1.w;
            uint4 pk;
            pk.x = pack2(v0.x, v0.y); pk.y = pack2(v0.z, v0.w);
            pk.z = pack2(v1.x, v1.y); pk.w = pack2(v1.z, v1.w);
            STS128(sbase + SMEM_A + swz((uint32_t)(tid * ROW_BYTES + j * 16)), pk);
        }
        x2s[tid] = x2;
    }
    __syncthreads();

    int p = 0;
    for (; tile < NTILES; tile += GRID) {
        const int row0 = tile * M_TILE;
        const int next = tile + GRID;
        const uint32_t abase = sbase + SMEM_A + (uint32_t)(p * 16384);
        const float* x2cur = x2s + p * M_TILE;

        // ---- prefetch next tile: LDG + pack into registers (overlaps MMA below) ----
        uint4 pf[8];
        float pfx2 = 0.f;
        if (tid < M_TILE && next < NTILES) {
            const float4* xr = reinterpret_cast<const float4*>(x + (size_t)(next * M_TILE + tid) * DDIM);
#pragma unroll
            for (int j = 0; j < 8; j++) {
                float4 v0 = xr[2 * j];
                float4 v1 = xr[2 * j + 1];
                pfx2 += v0.x * v0.x + v0.y * v0.y + v0.z * v0.z + v0.w * v0.w
                      + v1.x * v1.x + v1.y * v1.y + v1.z * v1.z + v1.w * v1.w;
                pf[j].x = pack2(v0.x, v0.y); pf[j].y = pack2(v0.z, v0.w);
                pf[j].z = pack2(v1.x, v1.y); pf[j].w = pack2(v1.z, v1.w);
            }
        }

        // ---- 8 m-fragments of 16 rows; every warp covers all rows, its 32 cols ----
#pragma unroll 1
        for (int mf = 0; mf < 8; mf++) {
            uint32_t a[4][4];
            const uint32_t arow = (uint32_t)(mf * 16 + (lid & 15));
#pragma unroll
            for (int k = 0; k < 4; k++) {
                uint32_t kbyte = (uint32_t)(k * 32 + ((lid >> 4) * 16));
                LDMATRIX_X4(a[k][0], a[k][1], a[k][2], a[k][3],
                            abase + swz(arow * ROW_BYTES + kbyte));
            }

            float acc[4][4];
#pragma unroll
            for (int nf = 0; nf < 4; nf++) {
                acc[nf][0] = 0.f; acc[nf][1] = 0.f; acc[nf][2] = 0.f; acc[nf][3] = 0.f;
#pragma unroll
                for (int k = 0; k < 4; k++) {
                    MMA16816(acc[nf][0], acc[nf][1], acc[nf][2], acc[nf][3],
                             a[k][0], a[k][1], a[k][2], a[k][3],
                             breg[nf][k][0], breg[nf][k][1]);
                }
            }

            // fused epilogue
            const int r0 = mf * 16 + (lid >> 2);
            const int r1 = r0 + 8;
            const float hx20 = 0.5f * x2cur[r0];
            const float hx21 = 0.5f * x2cur[r1];
            float acc0 = 0.f, acc1 = 0.f;
#pragma unroll
            for (int nf = 0; nf < 4; nf++) {
#pragma unroll
                for (int j = 0; j < 2; j++) {
                    float e0 = fmaf(k1v[nf][j], acc[nf][j] - hx20, kkv[nf][j]);
                    if (e0 > -126.f)
                        acc0 = fmaf(ex2f(fminf(e0, 0.f)), wv[nf][j], acc0);
                    float e1 = fmaf(k1v[nf][j], acc[nf][2 + j] - hx21, kkv[nf][j]);
                    if (e1 > -126.f)
                        acc1 = fmaf(ex2f(fminf(e1, 0.f)), wv[nf][j], acc1);
                }
            }
            acc0 += __shfl_xor_sync(0xffffffffu, acc0, 1);
            acc0 += __shfl_xor_sync(0xffffffffu, acc0, 2);
            acc1 += __shfl_xor_sync(0xffffffffu, acc1, 1);
            acc1 += __shfl_xor_sync(0xffffffffu, acc1, 2);
            if ((lid & 3) == 0) {
                part[wid * M_TILE + r0] = acc0;
                part[wid * M_TILE + r1] = acc1;
            }
        }

        __syncthreads();   // part complete; everyone done reading buf p

        // final per-row sum + store
        if (tid < M_TILE) {
            float s = bval;
#pragma unroll
            for (int w = 0; w < NWARPS; w++) s += part[w * M_TILE + tid];
            out[row0 + tid] = s;
        }

        // store prefetched tile into the other buffer
        if (tid < M_TILE && next < NTILES) {
            const uint32_t nbase = sbase + SMEM_A + (uint32_t)((p ^ 1) * 16384);
#pragma unroll
            for (int j = 0; j < 8; j++) {
                STS128(nbase + swz((uint32_t)(tid * ROW_BYTES + j * 16)), pf[j]);
            }
            x2s[(p ^ 1) * M_TILE + tid] = pfx2;
        }
        __syncthreads();   // next buffer ready
        p ^= 1;
    }
}

extern "C" void kernel_launch(void* const* d_in, const int* in_sizes, int n_in,
                              void* d_out, int out_size) {
    const float* x       = (const float*)d_in[0];
    const float* centres = (const float*)d_in[1];
    const float* sigmas  = (const float*)d_in[2];
    const float* W       = (const float*)d_in[3];
    const float* b       = (const float*)d_in[4];
    float* out = (float*)d_out;

    cudaFuncSetAttribute(rbfn_kernel, cudaFuncAttributeMaxDynamicSharedMemorySize, SMEM_TOTAL);
    rbfn_kernel<<<GRID, NTHREADS, SMEM_TOTAL>>>(x, centres, sigmas, W, b, out);
}